// round 16
// baseline (speedup 1.0000x reference)
#include <cuda_runtime.h>
#include <cuda_fp16.h>
#include <math.h>
#include <stdint.h>

// ---------------- problem constants ----------------
#define BB   16
#define TT   32
#define NN_  512
#define CC   128
#define HH   128
#define HLL  512
#define G4   2048
#define DD   65536
#define TNH  ((long)TT*NN_*HH)
#define EPSN 1e-5f
#define SPLITK0 16
#define LBLK 128
#define LTHR 256
#define BARSTR 32

// ---------------- device scratch ----------------
__device__ float g_d[NN_];
__device__ float g_tmp[BB*TT*NN_*HH];            // GN inputs; then split-K partials
__device__ float g_Z0[(long)BB*TT*G4];
__device__ float g_y0f[TT*HLL*BB];               // layer0 output, [t][j][b] fp32
__device__ __align__(16) float g_hA0[BB*HLL], g_hB0[BB*HLL];   // [HLL][BB]
__device__ __align__(16) float g_hA1[BB*HLL], g_hB1[BB*HLL];
__device__ unsigned g_bars[2*BARSTR];

__device__ __half g_x16  [BB*TT*NN_*CC];
__device__ __half g_hw16 [BB*TT*NN_*HH];
__device__ __half g_h116 [BB*TT*NN_*HH];
__device__ __half g_h216 [BB*TT*NN_*HH];
__device__ __half g_W116 [TT*CC*HH];
__device__ __half g_W216 [TT*HH*HH];
__device__ __half g_Wih016[(long)G4*DD];
__device__ __half g_M16  [NN_*NN_];

// ---------------- helpers ----------------
__device__ __forceinline__ float sigf(float x) { return 1.0f/(1.0f+expf(-x)); }
__device__ __forceinline__ void cp16(uint32_t saddr, const void* g) {
    asm volatile("cp.async.cg.shared.global [%0], [%1], 16;" :: "r"(saddr), "l"(g));
}
__device__ __forceinline__ void stcg(float* p, float v) {
    asm volatile("st.global.cg.f32 [%0], %1;" :: "l"(p), "f"(v));
}
__device__ __forceinline__ float4 ldcg4(const float4* p) {
    float4 v;
    asm volatile("ld.global.cg.v4.f32 {%0,%1,%2,%3}, [%4];"
                 : "=f"(v.x), "=f"(v.y), "=f"(v.z), "=f"(v.w) : "l"(p));
    return v;
}
__device__ __forceinline__ void ldm_x4(uint32_t* r, uint32_t a) {
    asm volatile("ldmatrix.sync.aligned.m8n8.x4.shared.b16 {%0,%1,%2,%3}, [%4];"
                 : "=r"(r[0]), "=r"(r[1]), "=r"(r[2]), "=r"(r[3]) : "r"(a));
}
__device__ __forceinline__ void ldm_x4t(uint32_t* r, uint32_t a) {
    asm volatile("ldmatrix.sync.aligned.m8n8.x4.trans.shared.b16 {%0,%1,%2,%3}, [%4];"
                 : "=r"(r[0]), "=r"(r[1]), "=r"(r[2]), "=r"(r[3]) : "r"(a));
}
__device__ __forceinline__ void mma16816(float* d, const uint32_t* a, const uint32_t* b) {
    asm volatile("mma.sync.aligned.m16n8k16.row.col.f32.f16.f16.f32 "
                 "{%0,%1,%2,%3},{%4,%5,%6,%7},{%8,%9},{%0,%1,%2,%3};"
                 : "+f"(d[0]), "+f"(d[1]), "+f"(d[2]), "+f"(d[3])
                 : "r"(a[0]), "r"(a[1]), "r"(a[2]), "r"(a[3]), "r"(b[0]), "r"(b[1]));
}

// ---------------- fp32 -> fp16 ----------------
__global__ void f2h_kernel(const float* __restrict__ s, __half* __restrict__ d, long n) {
    long i = ((long)blockIdx.x*blockDim.x + threadIdx.x)*4;
    if (i < n) {
        float4 v = *(const float4*)&s[i];
        *(__half2*)&d[i]   = __floats2half2_rn(v.x, v.y);
        *(__half2*)&d[i+2] = __floats2half2_rn(v.z, v.w);
    }
}

// ---------------- graph normalization matrix ----------------
__global__ void deg_kernel(const float* __restrict__ adj, float* __restrict__ d) {
    int i = blockIdx.x*blockDim.x + threadIdx.x;
    if (i < NN_) {
        float s = 1.0f;
        for (int j = 0; j < NN_; j++) s += adj[(long)j*NN_ + i];
        d[i] = rsqrtf(s);
    }
}
__global__ void buildM_kernel(const float* __restrict__ adj, const float* __restrict__ d,
                              __half* __restrict__ M16) {
    int idx = blockIdx.x*blockDim.x + threadIdx.x;
    if (idx < NN_*NN_) {
        int j = idx >> 9, i = idx & (NN_-1);
        float a = adj[idx] + (i == j ? 1.0f : 0.0f);
        M16[idx] = __float2half(d[j]*a*d[i]);
    }
}

// ============================================================================
// FP16 GEMM (R12/R15, unchanged): CTA 128x128x64, 8 warps of 64x32, 3-stage
// cp.async, ldmatrix fragments, mma.m16n8k16, fp32 accum. 2 CTAs/SM.
// ============================================================================
#define HBM 128
#define HBN 128
#define HBK 64
#define HKP 72
#define HNP 136
#define HSA (HBM*HKP)
#define HSB 9216
#define HSTG ((HSA+HSB)*2)
#define HSMEM (3*HSTG)

extern __shared__ char hsm[];

template<bool BNN>
__global__ void __launch_bounds__(256, 2)
hgemm(const __half* __restrict__ Ab, const __half* __restrict__ Bb,
      const float* __restrict__ biasb, float* __restrict__ C32b, __half* __restrict__ C16b,
      int M, int N, int K,
      long sA, int modA, long sB, int modB, long sBias, int modBias,
      long sC, int splitK, long sSplit)
{
    int z = blockIdx.z;
    int batch = z / splitK, split = z - batch*splitK;
    const __half* A = Ab + (long)(batch % modA)*sA;
    const __half* B = Bb + (long)(batch % modB)*sB;
    const float* bias = biasb ? biasb + (long)(batch % modBias)*sBias : nullptr;
    float* C32 = C32b ? C32b + (long)batch*sC + (long)split*sSplit : nullptr;
    __half* C16 = C16b ? C16b + (long)batch*sC : nullptr;

    int kchunk = K/splitK, kbeg = split*kchunk, nk = kchunk/HBK;
    uint32_t sm = (uint32_t)__cvta_generic_to_shared(hsm);

    int tid = threadIdx.x, lane = tid & 31, warp = tid >> 5;
    int wm = (warp & 1)*64, wn = (warp >> 1)*32;
    int m0 = blockIdx.y*HBM, n0 = blockIdx.x*HBN;

    float acc[4][4][4];
    #pragma unroll
    for (int i = 0; i < 4; i++)
        #pragma unroll
        for (int j = 0; j < 4; j++)
            #pragma unroll
            for (int k = 0; k < 4; k++) acc[i][j][k] = 0.0f;

    int a_m[4], a_kc[4], b0i[4], b1i[4];
    #pragma unroll
    for (int i = 0; i < 4; i++) {
        int idx = tid + i*256;
        a_m[i] = idx >> 3; a_kc[i] = idx & 7;
        if (BNN) { b0i[i] = idx >> 4; b1i[i] = idx & 15; }
        else     { b0i[i] = idx >> 3; b1i[i] = idx & 7; }
    }

    auto issue = [&](int s, int kt) {
        int kg = kbeg + kt*HBK;
        uint32_t ba = sm + (uint32_t)s*HSTG;
        uint32_t bb = ba + HSA*2;
        #pragma unroll
        for (int i = 0; i < 4; i++)
            cp16(ba + (uint32_t)(a_m[i]*HKP + a_kc[i]*8)*2,
                 &A[(long)(m0 + a_m[i])*K + kg + a_kc[i]*8]);
        #pragma unroll
        for (int i = 0; i < 4; i++) {
            if (BNN)
                cp16(bb + (uint32_t)(b0i[i]*HNP + b1i[i]*8)*2,
                     &B[(long)(kg + b0i[i])*N + n0 + b1i[i]*8]);
            else
                cp16(bb + (uint32_t)(b0i[i]*HKP + b1i[i]*8)*2,
                     &B[(long)(n0 + b0i[i])*K + kg + b1i[i]*8]);
        }
    };

    issue(0, 0); asm volatile("cp.async.commit_group;");
    issue(1, 1); asm volatile("cp.async.commit_group;");

    uint32_t aoff[4];
    #pragma unroll
    for (int mt = 0; mt < 4; mt++)
        aoff[mt] = (uint32_t)((wm + mt*16 + (lane & 15))*HKP + (lane >> 4)*8)*2;
    int quad = lane >> 3;
    uint32_t boff[2];
    #pragma unroll
    for (int p = 0; p < 2; p++) {
        if (BNN)
            boff[p] = (uint32_t)(((quad & 1)*8 + (lane & 7))*HNP
                      + wn + p*16 + (quad >> 1)*8)*2;
        else
            boff[p] = (uint32_t)((wn + p*16 + (quad >> 1)*8 + (lane & 7))*HKP
                      + (quad & 1)*8)*2;
    }

    for (int kt = 0; kt < nk; kt++) {
        asm volatile("cp.async.wait_group 1;");
        __syncthreads();
        if (kt + 2 < nk) issue((kt + 2) % 3, kt + 2);
        asm volatile("cp.async.commit_group;");

        uint32_t sa = sm + (uint32_t)(kt % 3)*HSTG;
        uint32_t sb = sa + HSA*2;

        #pragma unroll
        for (int ks = 0; ks < 4; ks++) {
            uint32_t af[4][4];
            #pragma unroll
            for (int mt = 0; mt < 4; mt++) ldm_x4(af[mt], sa + aoff[mt] + ks*32);
            uint32_t bf[4][2];
            #pragma unroll
            for (int p = 0; p < 2; p++) {
                uint32_t r[4];
                if (BNN) ldm_x4t(r, sb + boff[p] + (uint32_t)ks*16*HNP*2);
                else     ldm_x4 (r, sb + boff[p] + ks*32);
                bf[p*2][0] = r[0]; bf[p*2][1] = r[1];
                bf[p*2+1][0] = r[2]; bf[p*2+1][1] = r[3];
            }
            #pragma unroll
            for (int mt = 0; mt < 4; mt++)
                #pragma unroll
                for (int nt = 0; nt < 4; nt++)
                    mma16816(acc[mt][nt], af[mt], bf[nt]);
        }
    }

    #pragma unroll
    for (int nt = 0; nt < 4; nt++) {
        int c0 = n0 + wn + nt*8 + (lane & 3)*2;
        float bv0 = bias ? bias[c0] : 0.0f;
        float bv1 = bias ? bias[c0+1] : 0.0f;
        #pragma unroll
        for (int mt = 0; mt < 4; mt++) {
            int r = m0 + wm + mt*16 + (lane >> 2);
            float v00 = acc[mt][nt][0] + bv0, v01 = acc[mt][nt][1] + bv1;
            float v10 = acc[mt][nt][2] + bv0, v11 = acc[mt][nt][3] + bv1;
            if (C16) {
                *(__half2*)&C16[(long)r*N + c0]     = __floats2half2_rn(v00, v01);
                *(__half2*)&C16[(long)(r+8)*N + c0] = __floats2half2_rn(v10, v11);
            } else {
                *(float2*)&C32[(long)r*N + c0]     = make_float2(v00, v01);
                *(float2*)&C32[(long)(r+8)*N + c0] = make_float2(v10, v11);
            }
        }
    }
}

// ---------------- split-K reduce + bias ----------------
__global__ void reduce_bias_kernel(const float* __restrict__ P, const float* __restrict__ bias,
                                   float* __restrict__ Z, long total, long stride, int splits)
{
    long idx = (long)blockIdx.x*blockDim.x + threadIdx.x;
    if (idx >= total) return;
    float s = bias[idx & (G4-1)];
    #pragma unroll 8
    for (int i = 0; i < splits; i++) s += P[(long)i*stride + idx];
    Z[idx] = s;
}

// ---------------- GraphNorm + residual + ReLU (fp32 or fp16 residual) ----------------
template<bool RES16>
__global__ void graphnorm_kernel(const float* __restrict__ hraw,
                                 const float* __restrict__ res32,
                                 const __half* __restrict__ res16,
                                 const float* __restrict__ w, const float* __restrict__ bias,
                                 const float* __restrict__ ms,
                                 __half* __restrict__ out16)
{
    long p = (long)blockIdx.x*blockDim.x + threadIdx.x;
    if (p >= TNH) return;
    int h = (int)(p & (HH-1));
    float v[BB];
    float mean = 0.0f;
    #pragma unroll
    for (int b = 0; b < BB; b++) { v[b] = hraw[(long)b*TNH + p]; mean += v[b]; }
    mean *= (1.0f/BB);
    float msv = ms[h], var = 0.0f;
    #pragma unroll
    for (int b = 0; b < BB; b++) { v[b] -= msv*mean; var += v[b]*v[b]; }
    var *= (1.0f/BB);
    float inv = rsqrtf(var + EPSN);
    float wv = w[h]*inv, bv = bias[h];
    #pragma unroll
    for (int b = 0; b < BB; b++) {
        float rr = RES16 ? __half2float(res16[(long)b*TNH + p]) : res32[(long)b*TNH + p];
        float r = fmaxf(wv*v[b] + bv + rr, 0.0f);
        out16[(long)b*TNH + p] = __float2half(r);
    }
}

// ---------------- zero barrier counters ----------------
__global__ void zero_bars_kernel(unsigned* bars) {
    int i = blockIdx.x*blockDim.x + threadIdx.x;
    if (i < 2*BARSTR) bars[i] = 0u;
}

// ============================================================================
// Fused dual-layer persistent LSTM, 256 blocks x 256 thr.
// Blocks 0..127  : layer 0 (proven R12 code; also writes y0 fp32 [t][j][b]).
// Blocks 128..255: layer 1; gate input computed in-kernel (Wih1 row in regs,
//                  y0 matvec'd from smem) — Z1 GEMM eliminated.
// Cross-layer sync: layer0 writers st.cg+fence, t0 atomicAdd(bar0) EVERY step;
// layer1 t0 volatile-polls bar0 >= 128*(t+1) before loading y0[t]. Layer0
// never waits on layer1; all 128 layer0 blocks fit wave 1 => deadlock-free.
// Dynamic smem: hs[8192] | y0s[8192] | red[2176] | gsum[256]  (75264 B).
// ============================================================================
#define LSW (HLL*BB)                       // 8192
#define LSMEM ((2*LSW + 8*16*17 + 256)*4)  // 75264 bytes

extern __shared__ float lsm[];

__global__ void __launch_bounds__(LTHR, 2)
lstm_dual(const float* __restrict__ Z0,
          const float* __restrict__ Whh0, const float* __restrict__ bhh0,
          const float* __restrict__ Wih1, const float* __restrict__ Whh1,
          const float* __restrict__ bih1, const float* __restrict__ bhh1,
          float* __restrict__ bufA0, float* __restrict__ bufB0,
          float* __restrict__ bufA1, float* __restrict__ bufB1,
          float* __restrict__ y0f,
          unsigned* __restrict__ bars)
{
    float* hs   = lsm;                 // [HLL][BB]
    float* y0s  = lsm + LSW;           // [HLL][BB] (layer1 only)
    float* red  = lsm + 2*LSW;         // [8*16*17]
    float* gsum = red + 8*16*17;       // [16*16]

    const int t = threadIdx.x;
    const int layer = blockIdx.x >> 7;
    const int blk = blockIdx.x & 127;
    const int c = t & 15, sub = t >> 4;
    const int warp = t >> 5;
    const int mh_local = c & 3, gate = c >> 2;
    const int m = gate*HLL + blk*4 + mh_local;

    unsigned* bar0 = bars;
    unsigned* bar1 = bars + BARSTR;

    const float* Whh = layer ? Whh1 : Whh0;
    float w[32];
    {
        const float* wr = Whh + (long)m*HLL + sub*32;
        #pragma unroll
        for (int j = 0; j < 32; j++) w[j] = wr[j];
    }
    float wih[32];
    if (layer) {
        const float* wr = Wih1 + (long)m*HLL + sub*32;
        #pragma unroll
        for (int j = 0; j < 32; j++) wih[j] = wr[j];
    }

    const int ub = t & 15;
    const int uml = (t >> 4) & 3;
    const int umh = blk*4 + uml;
    float creg = 0.0f;
    float bi = 0.f, bf = 0.f, bg = 0.f, bo = 0.f;
    if (t < 64) {
        if (layer) {
            bi = bih1[0*HLL + umh] + bhh1[0*HLL + umh];
            bf = bih1[1*HLL + umh] + bhh1[1*HLL + umh];
            bg = bih1[2*HLL + umh] + bhh1[2*HLL + umh];
            bo = bih1[3*HLL + umh] + bhh1[3*HLL + umh];
        } else {
            bi = bhh0[0*HLL + umh]; bf = bhh0[1*HLL + umh];
            bg = bhh0[2*HLL + umh]; bo = bhh0[3*HLL + umh];
        }
    }

    float* bufA = layer ? bufA1 : bufA0;
    float* bufB = layer ? bufB1 : bufB0;

    for (int i = t; i < LSW; i += LTHR) hs[i] = 0.0f;
    __syncthreads();

    unsigned target = 0;

    for (int step = 0; step < TT; step++) {
        float zi = 0.f, zf = 0.f, zg = 0.f, zo = 0.f;
        if (!layer && t < 64) {
            long zb = ((long)ub*TT + step)*G4;
            zi = __ldcs(&Z0[zb + 0*HLL + umh]); zf = __ldcs(&Z0[zb + 1*HLL + umh]);
            zg = __ldcs(&Z0[zb + 2*HLL + umh]); zo = __ldcs(&Z0[zb + 3*HLL + umh]);
        }

        if (layer) {
            // wait for layer0's y0[step], then load to smem
            if (t == 0) {
                unsigned need = (unsigned)(LBLK*(step + 1));
                while (*(volatile unsigned*)bar0 < need) { }
            }
            __syncthreads();
            const float4* ys = (const float4*)&y0f[(long)step*LSW];
            float4* yd = (float4*)y0s;
            #pragma unroll
            for (int q = t; q < LSW/4; q += LTHR)
                yd[q] = ldcg4(&ys[q]);
            __syncthreads();
        }

        float acc[BB];
        #pragma unroll
        for (int b = 0; b < BB; b++) acc[b] = 0.0f;
        if (layer) {
            #pragma unroll
            for (int j = 0; j < 32; j++) {
                float wv = w[j], wv2 = wih[j];
                const float* hr = &hs[(sub*32 + j)*BB];
                const float* yr = &y0s[(sub*32 + j)*BB];
                #pragma unroll
                for (int b = 0; b < BB; b += 4) {
                    float4 h4 = *(const float4*)&hr[b];
                    float4 y4 = *(const float4*)&yr[b];
                    acc[b+0] += wv*h4.x + wv2*y4.x;
                    acc[b+1] += wv*h4.y + wv2*y4.y;
                    acc[b+2] += wv*h4.z + wv2*y4.z;
                    acc[b+3] += wv*h4.w + wv2*y4.w;
                }
            }
        } else {
            #pragma unroll
            for (int j = 0; j < 32; j++) {
                float wv = w[j];
                const float* hr = &hs[(sub*32 + j)*BB];
                #pragma unroll
                for (int b = 0; b < BB; b += 4) {
                    float4 h4 = *(const float4*)&hr[b];
                    acc[b+0] += wv*h4.x; acc[b+1] += wv*h4.y;
                    acc[b+2] += wv*h4.z; acc[b+3] += wv*h4.w;
                }
            }
        }
        #pragma unroll
        for (int b = 0; b < BB; b++)
            acc[b] += __shfl_down_sync(0xffffffffu, acc[b], 16);
        if ((t & 31) < 16) {
            float* rp = &red[(warp*16 + c)*17];
            #pragma unroll
            for (int b = 0; b < BB; b++) rp[b] = acc[b];
        }
        __syncthreads();
        {
            int c2 = t & 15, b2 = t >> 4;
            float s = 0.0f;
            #pragma unroll
            for (int s2 = 0; s2 < 8; s2++) s += red[(s2*16 + c2)*17 + b2];
            gsum[c2*16 + b2] = s;
        }
        __syncthreads();

        if (t < 64) {
            float gi = sigf (zi + gsum[(0*4+uml)*16 + ub] + bi);
            float gf = sigf (zf + gsum[(1*4+uml)*16 + ub] + bf);
            float gg = tanhf(zg + gsum[(2*4+uml)*16 + ub] + bg);
            float go = sigf (zo + gsum[(3*4+uml)*16 + ub] + bo);
            creg = gf*creg + gi*gg;
            float hn = go*tanhf(creg);
            float* hout = ((step+1) & 1) ? bufB : bufA;
            stcg(&hout[umh*BB + ub], hn);
            if (!layer) stcg(&y0f[(long)step*LSW + umh*BB + ub], hn);
            __threadfence();
        }
        __syncthreads();

        target += LBLK;
        if (!layer) {
            // arrive EVERY step (layer1 waits on all 32); poll except last
            if (t == 0) {
                atomicAdd(bar0, 1u);
                if (step + 1 < TT) {
                    while (*(volatile unsigned*)bar0 < target) { }
                }
            }
            __syncthreads();
        } else if (step + 1 < TT) {
            if (t == 0) {
                atomicAdd(bar1, 1u);
                while (*(volatile unsigned*)bar1 < target) { }
            }
            __syncthreads();
        }

        if (step + 1 < TT) {
            const float4* hin = (const float4*)(((step+1) & 1) ? bufB : bufA);
            float4* hsd = (float4*)hs;
            #pragma unroll
            for (int q = t; q < LSW/4; q += LTHR)
                hsd[q] = ldcg4(&hin[q]);
            __syncthreads();
        }
    }
}

// ---------------- final projection (h in [j][b] layout) ----------------
__global__ void proj_kernel(const float* __restrict__ h, const float* __restrict__ Wp,
                            const float* __restrict__ bp, float* __restrict__ out)
{
    int tid = threadIdx.x;
    int b = tid >> 3, o = tid & 7;
    float s = bp[o];
    const float* wr = Wp + o*HLL;
    for (int m = 0; m < HLL; m++) s += h[m*BB + b]*wr[m];
    out[b*8 + o] = s;
}

// ---------------- launch ----------------
extern "C" void kernel_launch(void* const* d_in, const int* in_sizes, int n_in,
                              void* d_out, int out_size)
{
    const float* x    = (const float*)d_in[0];
    const float* adj  = (const float*)d_in[1];
    const float* W1   = (const float*)d_in[2];
    const float* b1   = (const float*)d_in[3];
    const float* W2   = (const float*)d_in[4];
    const float* b2   = (const float*)d_in[5];
    const float* gn1w = (const float*)d_in[6];
    const float* gn1b = (const float*)d_in[7];
    const float* gn1m = (const float*)d_in[8];
    const float* gn2w = (const float*)d_in[9];
    const float* gn2b = (const float*)d_in[10];
    const float* gn2m = (const float*)d_in[11];
    const float* Wih0 = (const float*)d_in[12];
    const float* Whh0 = (const float*)d_in[13];
    const float* bih0 = (const float*)d_in[14];
    const float* bhh0 = (const float*)d_in[15];
    const float* Wih1 = (const float*)d_in[16];
    const float* Whh1 = (const float*)d_in[17];
    const float* bih1 = (const float*)d_in[18];
    const float* bhh1 = (const float*)d_in[19];
    const float* Wp   = (const float*)d_in[20];
    const float* bp   = (const float*)d_in[21];
    float* out = (float*)d_out;

    float *pD, *pTmp, *pZ0, *pY0F, *pHA0, *pHB0, *pHA1, *pHB1;
    unsigned* pBars;
    __half *pX16, *pHw16, *pH116, *pH216, *pW116, *pW216, *pWih016, *pM16;
    cudaGetSymbolAddress((void**)&pD,     g_d);
    cudaGetSymbolAddress((void**)&pTmp,   g_tmp);
    cudaGetSymbolAddress((void**)&pZ0,    g_Z0);
    cudaGetSymbolAddress((void**)&pY0F,   g_y0f);
    cudaGetSymbolAddress((void**)&pHA0,   g_hA0);
    cudaGetSymbolAddress((void**)&pHB0,   g_hB0);
    cudaGetSymbolAddress((void**)&pHA1,   g_hA1);
    cudaGetSymbolAddress((void**)&pHB1,   g_hB1);
    cudaGetSymbolAddress((void**)&pBars,  g_bars);
    cudaGetSymbolAddress((void**)&pX16,   g_x16);
    cudaGetSymbolAddress((void**)&pHw16,  g_hw16);
    cudaGetSymbolAddress((void**)&pH116,  g_h116);
    cudaGetSymbolAddress((void**)&pH216,  g_h216);
    cudaGetSymbolAddress((void**)&pW116,  g_W116);
    cudaGetSymbolAddress((void**)&pW216,  g_W216);
    cudaGetSymbolAddress((void**)&pWih016,g_Wih016);
    cudaGetSymbolAddress((void**)&pM16,   g_M16);

    cudaFuncSetAttribute(hgemm<true>,  cudaFuncAttributeMaxDynamicSharedMemorySize, HSMEM);
    cudaFuncSetAttribute(hgemm<false>, cudaFuncAttributeMaxDynamicSharedMemorySize, HSMEM);
    cudaFuncSetAttribute(lstm_dual,    cudaFuncAttributeMaxDynamicSharedMemorySize, LSMEM);

    // converts + M + barriers (Wih1 convert no longer needed)
    f2h_kernel<<<32768, 256>>>(x, pX16, (long)BB*TT*NN_*CC);
    f2h_kernel<<<512, 256>>>(W1, pW116, (long)TT*CC*HH);
    f2h_kernel<<<512, 256>>>(W2, pW216, (long)TT*HH*HH);
    f2h_kernel<<<131072, 256>>>(Wih0, pWih016, (long)G4*DD);
    deg_kernel<<<2, 256>>>(adj, pD);
    buildM_kernel<<<(NN_*NN_)/256, 256>>>(adj, pD, pM16);
    zero_bars_kernel<<<1, 64>>>(pBars);

    const long sX = (long)NN_*HH;   // 65536
    const int  BT = BB*TT;          // 512
    const long zTot = (long)BT*G4;  // 1,048,576

    // ---- GCN layer 1 ----
    hgemm<true><<<dim3(1, NN_/HBM, BT), 256, HSMEM>>>(pX16, pW116, nullptr, nullptr, pHw16,
        NN_, HH, CC, sX, BT, (long)CC*HH, TT, 0, 1, sX, 1, 0);
    hgemm<true><<<dim3(1, NN_/HBM, BT), 256, HSMEM>>>(pM16, pHw16, b1, pTmp, nullptr,
        NN_, HH, NN_, 0, 1, sX, BT, HH, TT, sX, 1, 0);
    graphnorm_kernel<false><<<(int)(TNH/256), 256>>>(pTmp, x, nullptr,
        gn1w, gn1b, gn1m, pH116);

    // ---- GCN layer 2 ----
    hgemm<true><<<dim3(1, NN_/HBM, BT), 256, HSMEM>>>(pH116, pW216, nullptr, nullptr, pHw16,
        NN_, HH, HH, sX, BT, (long)HH*HH, TT, 0, 1, sX, 1, 0);
    hgemm<true><<<dim3(1, NN_/HBM, BT), 256, HSMEM>>>(pM16, pHw16, b2, pTmp, nullptr,
        NN_, HH, NN_, 0, 1, sX, BT, HH, TT, sX, 1, 0);
    graphnorm_kernel<true><<<(int)(TNH/256), 256>>>(pTmp, nullptr, pH116,
        gn2w, gn2b, gn2m, pH216);

    // ---- LSTM layer 0 input GEMM (split-K=16), reduce ----
    hgemm<false><<<dim3(G4/HBN, BT/HBM, SPLITK0), 256, HSMEM>>>(pH216, pWih016, nullptr, pTmp, nullptr,
        BT, G4, DD, 0, 1, 0, 1, 0, 1, 0, SPLITK0, zTot);
    reduce_bias_kernel<<<(int)(zTot/256), 256>>>(pTmp, bih0, pZ0, zTot, zTot, SPLITK0);

    // ---- fused dual-layer LSTM (layer1 pipelined behind layer0) ----
    lstm_dual<<<2*LBLK, LTHR, LSMEM>>>(pZ0, Whh0, bhh0, Wih1, Whh1, bih1, bhh1,
                                       pHA0, pHB0, pHA1, pHB1, pY0F, pBars);

    // ---- projection (final h of layer1 in bufA1) ----
    proj_kernel<<<1, 128>>>(pHA1, Wp, bp, out);
}